// round 2
// baseline (speedup 1.0000x reference)
#include <cuda_runtime.h>
#include <math.h>

#define BATCH 4
#define KNB 24

// ---------------- scratch (device globals; no runtime allocation) ----------------
__device__ int    g_fps[BATCH * 2048];
__device__ int    g_knn[BATCH * 2048 * KNB];
__device__ float  g_lc0[BATCH * 2048 * 3];     // stage0 centers == stage1 xyz
__device__ float  g_lc1[BATCH * 1024 * 3];     // stage1 centers
__device__ float  g_lcx[BATCH * 2048 * 72];    // lc features (same size both stages)
__device__ float  g_feats0[BATCH * 4096 * 72]; // x transposed to [B,N,C]
__device__ float  g_feats1[BATCH * 2048 * 144];// stage0 output in [B,N,C] layout
__device__ float  g_pool[BATCH * 144 * 2048];  // pooled [B,2C,G] (same size both stages)
__device__ double g_acc[4];                    // s_x, ss_x, s_xyz, ss_xyz
__device__ float  g_inv[2];                    // 1/(std_x+1e-5), 1/(std_xyz+1e-5)

// ---------------- helpers ----------------
__device__ __forceinline__ double warp_sum_d(double v) {
#pragma unroll
    for (int off = 16; off > 0; off >>= 1)
        v += __shfl_down_sync(0xffffffffu, v, off);
    return v;
}

// ---------------- transpose [B,C,N] -> [B,N,C] ----------------
__global__ void transpose_kernel(const float* __restrict__ x, float* __restrict__ feats,
                                 int C, int N) {
    int i = blockIdx.x * blockDim.x + threadIdx.x;
    int total = BATCH * C * N;
    if (i >= total) return;
    int b = i / (C * N);
    int rr = i - b * (C * N);
    int c = rr / N;
    int n = rr - c * N;
    feats[((size_t)b * N + n) * C + c] = x[i];
}

// ---------------- furthest point sampling (exact ref arithmetic, first-max ties) ----
template <int N, int G>
__global__ __launch_bounds__(256) void fps_kernel(const float* __restrict__ xyz,
                                                  int* __restrict__ out_idx) {
    constexpr int T = 256;
    constexpr int PPT = N / T;
    const int b = blockIdx.x;
    const int tid = threadIdx.x;
    const float* xb = xyz + (size_t)b * N * 3;

    float px[PPT], py[PPT], pz[PPT], dd[PPT];
#pragma unroll
    for (int i = 0; i < PPT; ++i) {
        int n = tid * PPT + i;
        px[i] = xb[n * 3 + 0];
        py[i] = xb[n * 3 + 1];
        pz[i] = xb[n * 3 + 2];
        dd[i] = 1e10f;
    }
    __shared__ float s_val[8];
    __shared__ int s_idx[8];
    __shared__ int s_far;

    int far = 0;
    for (int m = 0; m < G; ++m) {
        if (tid == 0) out_idx[(size_t)b * G + m] = far;
        float cx = __ldg(xb + far * 3 + 0);
        float cy = __ldg(xb + far * 3 + 1);
        float cz = __ldg(xb + far * 3 + 2);
        float bv = -1.0f;
        int bi = 0;
#pragma unroll
        for (int i = 0; i < PPT; ++i) {
            float dx = __fsub_rn(px[i], cx);
            float dy = __fsub_rn(py[i], cy);
            float dz = __fsub_rn(pz[i], cz);
            float d = __fadd_rn(__fadd_rn(__fmul_rn(dx, dx), __fmul_rn(dy, dy)),
                                __fmul_rn(dz, dz));
            float nd = fminf(dd[i], d);
            dd[i] = nd;
            if (nd > bv) { bv = nd; bi = tid * PPT + i; }   // first max within chunk
        }
#pragma unroll
        for (int off = 16; off > 0; off >>= 1) {
            float ov = __shfl_down_sync(0xffffffffu, bv, off);
            int oi = __shfl_down_sync(0xffffffffu, bi, off);
            if (ov > bv || (ov == bv && oi < bi)) { bv = ov; bi = oi; }
        }
        if ((tid & 31) == 0) { s_val[tid >> 5] = bv; s_idx[tid >> 5] = bi; }
        __syncthreads();
        if (tid == 0) {
#pragma unroll
            for (int w = 1; w < 8; ++w)
                if (s_val[w] > bv || (s_val[w] == bv && s_idx[w] < bi)) {
                    bv = s_val[w];
                    bi = s_idx[w];
                }
            s_far = bi;
        }
        __syncthreads();
        far = s_far;
    }
}

// ---------------- gather centers ----------------
template <int N, int G, int C>
__global__ void gather_lc_kernel(const float* __restrict__ xyz,
                                 const float* __restrict__ feats,
                                 const int* __restrict__ fps, float* __restrict__ lcxyz,
                                 float* __restrict__ lcx) {
    int i = blockIdx.x * blockDim.x + threadIdx.x;
    const int per = C + 3;
    int total = BATCH * G * per;
    if (i >= total) return;
    int bg = i / per;
    int c = i - bg * per;
    int b = bg / G;
    int idx = fps[bg];
    if (c < C)
        lcx[(size_t)bg * C + c] = feats[((size_t)b * N + idx) * C + c];
    else
        lcxyz[(size_t)bg * 3 + (c - C)] = xyz[((size_t)b * N + idx) * 3 + (c - C)];
}

// ---------------- kNN: exact ref distance formula, stable (lowest-index) ties ------
template <int N, int G>
__global__ __launch_bounds__(256) void knn_kernel(const float* __restrict__ xyz,
                                                  const float* __restrict__ lc,
                                                  int* __restrict__ knn) {
    constexpr int T = 256;
    constexpr int PPT = N / T;
    const int bg = blockIdx.x;
    const int b = bg / G;
    const int tid = threadIdx.x;
    __shared__ float sd[N];
    __shared__ float s_val[8];
    __shared__ int s_idx[8];
    const float* xb = xyz + (size_t)b * N * 3;
    float cx = lc[bg * 3 + 0], cy = lc[bg * 3 + 1], cz = lc[bg * 3 + 2];
    float sc = __fadd_rn(__fadd_rn(__fmul_rn(cx, cx), __fmul_rn(cy, cy)),
                         __fmul_rn(cz, cz));
#pragma unroll
    for (int i = 0; i < PPT; ++i) {
        int n = tid * PPT + i;
        float xx = xb[n * 3 + 0], xy = xb[n * 3 + 1], xz = xb[n * 3 + 2];
        float sx = __fadd_rn(__fadd_rn(__fmul_rn(xx, xx), __fmul_rn(xy, xy)),
                             __fmul_rn(xz, xz));
        float dt = __fadd_rn(__fadd_rn(__fmul_rn(cx, xx), __fmul_rn(cy, xy)),
                             __fmul_rn(cz, xz));
        float d = __fadd_rn(__fsub_rn(sc, __fmul_rn(2.0f, dt)), sx);
        sd[n] = d;
    }
    __syncthreads();
    const float INF = __int_as_float(0x7f800000);
    for (int k = 0; k < KNB; ++k) {
        float bv = INF;
        int bi = N;
#pragma unroll
        for (int i = 0; i < PPT; ++i) {
            int n = tid * PPT + i;
            float v = sd[n];
            if (v < bv) { bv = v; bi = n; }   // first min within chunk
        }
#pragma unroll
        for (int off = 16; off > 0; off >>= 1) {
            float ov = __shfl_down_sync(0xffffffffu, bv, off);
            int oi = __shfl_down_sync(0xffffffffu, bi, off);
            if (ov < bv || (ov == bv && oi < bi)) { bv = ov; bi = oi; }
        }
        if ((tid & 31) == 0) { s_val[tid >> 5] = bv; s_idx[tid >> 5] = bi; }
        __syncthreads();
        if (tid == 0) {
#pragma unroll
            for (int w = 1; w < 8; ++w)
                if (s_val[w] < bv || (s_val[w] == bv && s_idx[w] < bi)) {
                    bv = s_val[w];
                    bi = s_idx[w];
                }
            knn[(size_t)bg * KNB + k] = bi;
            sd[bi] = INF;
        }
        __syncthreads();
    }
}

// ---------------- global std statistics ----------------
__global__ void zero_acc_kernel() {
    if (threadIdx.x < 4) g_acc[threadIdx.x] = 0.0;
}

template <int N, int G, int C>
__global__ __launch_bounds__(256) void stats_kernel(const float* __restrict__ xyz,
                                                    const float* __restrict__ feats,
                                                    const int* __restrict__ knn,
                                                    const float* __restrict__ lcxyz,
                                                    const float* __restrict__ lcx) {
    const int P = BATCH * G * KNB;
    int p = blockIdx.x * blockDim.x + threadIdx.x;
    float s1 = 0.f, ss1 = 0.f, s2 = 0.f, ss2 = 0.f;
    if (p < P) {
        int b = p / (G * KNB);
        int rg = p - b * (G * KNB);
        int g = rg / KNB;
        int bg = b * G + g;
        int kidx = knn[p];
        const float* kp = xyz + ((size_t)b * N + kidx) * 3;
        const float* lp = lcxyz + (size_t)bg * 3;
#pragma unroll
        for (int j = 0; j < 3; ++j) {
            float d = kp[j] - lp[j];
            s2 += d;
            ss2 += d * d;
        }
        const float* kf = feats + ((size_t)b * N + kidx) * C;
        const float* lf = lcx + (size_t)bg * C;
        for (int c = 0; c < C; ++c) {
            float d = kf[c] - lf[c];
            s1 += d;
            ss1 += d * d;
        }
    }
    __shared__ double sh[4][8];
    double v[4] = {(double)s1, (double)ss1, (double)s2, (double)ss2};
#pragma unroll
    for (int q = 0; q < 4; ++q) {
        double r = warp_sum_d(v[q]);
        if ((threadIdx.x & 31) == 0) sh[q][threadIdx.x >> 5] = r;
    }
    __syncthreads();
    if (threadIdx.x == 0) {
#pragma unroll
        for (int q = 0; q < 4; ++q) {
            double t = 0;
#pragma unroll
            for (int w = 0; w < 8; ++w) t += sh[q][w];
            atomicAdd(&g_acc[q], t);
        }
    }
}

__global__ void finalize_kernel(double n1, double n2) {
    double v1 = (g_acc[1] - g_acc[0] * g_acc[0] / n1) / (n1 - 1.0);
    double v2 = (g_acc[3] - g_acc[2] * g_acc[2] / n2) / (n2 - 1.0);
    g_inv[0] = 1.0f / ((float)sqrt(v1) + 1e-5f);
    g_inv[1] = 1.0f / ((float)sqrt(v2) + 1e-5f);
}

// ---------------- fused LGA + pooling: 1 thread per output channel ---------------
// pooled[b,ch,g] = k_anp(w)+mean_K(w) = 2*mean_K(w)  (k_anp is identity-mean)
template <int N, int G, int C>
__global__ void main_kernel(const float* __restrict__ xyz, const float* __restrict__ feats,
                            const float* __restrict__ Bmat, const int* __restrict__ knn,
                            const float* __restrict__ lcxyz, const float* __restrict__ lcx,
                            float* __restrict__ pool) {
    constexpr int C2 = 2 * C;
    constexpr int F = C / 3;   // my_dim/(2*3)
    constexpr int CH = C / 2;
    const int bg = blockIdx.x;
    const int b = bg / G;
    const int g = bg - b * G;
    const int ch = threadIdx.x;
    if (ch >= C2) return;

    const int c3 = ch / (2 * F);
    const int r = ch - c3 * (2 * F);
    const int f = r >> 1;
    const int s = r & 1;
    const float de = powf(100.0f, (float)f / (float)F);
    const float lx = lcxyz[bg * 3 + 0];
    const float ly = lcxyz[bg * 3 + 1];
    const float lz = lcxyz[bg * 3 + 2];
    const float lcv = (c3 == 0) ? lx : ((c3 == 1) ? ly : lz);
    const float divL = 1000.0f * lcv / de;
    const float peL = s ? cosf(divL) : sinf(divL);
    const float inv_x = g_inv[0];
    const float inv_p = g_inv[1];

    const bool isFourier = (ch >= C);
    float lcf = 0.0f;
    float B0c = 0, B1c = 0, B2c = 0, B3c = 0, B4c = 0, B5c = 0, B6c = 0;
    bool isSin = false;
    if (!isFourier) {
        lcf = lcx[(size_t)bg * C + ch];
    } else {
        int jj = ch - C;
        isSin = (jj < CH);
        int j = isSin ? jj : (jj - CH);
        B0c = Bmat[0 * CH + j];
        B1c = Bmat[1 * CH + j];
        B2c = Bmat[2 * CH + j];
        B3c = Bmat[3 * CH + j];
        B4c = Bmat[4 * CH + j];
        B5c = Bmat[5 * CH + j];
        B6c = Bmat[6 * CH + j];
    }
    const float* xb = xyz + (size_t)b * N * 3;
    const int* kn = knn + (size_t)bg * KNB;
    float acc = 0.0f;
#pragma unroll 1
    for (int k = 0; k < KNB; ++k) {
        int kidx = kn[k];
        float kx = __ldg(xb + kidx * 3 + 0);
        float ky = __ldg(xb + kidx * 3 + 1);
        float kz = __ldg(xb + kidx * 3 + 2);
        float nx = (kx - lx) * inv_p;
        float ny = (ky - ly) * inv_p;
        float nz = (kz - lz) * inv_p;
        float nc = (c3 == 0) ? nx : ((c3 == 1) ? ny : nz);
        float divK = 1000.0f * nc / de;
        float pe = (s ? cosf(divK) : sinf(divK)) + peL;
        float a;
        if (!isFourier) {
            a = (feats[((size_t)b * N + kidx) * C + ch] - lcf) * inv_x;
        } else {
            float crx = ny * lz - nz * ly;
            float cry = nz * lx - nx * lz;
            float crz = nx * ly - ny * lx;
            float dt = nx * lx + ny * ly + nz * lz;
            float proj = B0c * nx + B1c * ny + B2c * nz + B3c * crx + B4c * cry +
                         B5c * crz + B6c * dt;
            proj *= 6.283185307179586f;
            float t = isSin ? sinf(proj) : cosf(proj);
            float t2 = t * t;
            a = t * t2 * t2;   // sign(t)*|t|^5
        }
        acc += (a + pe) * pe;
    }
    float mval = acc * (1.0f / 24.0f);
    pool[((size_t)b * C2 + ch) * G + g] = mval + mval;
}

// ---------------- BatchNorm (training-mode batch stats) + exact GELU --------------
template <int CO, int G, bool FOUT>
__global__ __launch_bounds__(256) void bn_kernel(const float* __restrict__ pool,
                                                 const float* __restrict__ gamma,
                                                 const float* __restrict__ beta,
                                                 float* __restrict__ out) {
    const int ch = blockIdx.x;
    const int tid = threadIdx.x;
    const int M = BATCH * G;
    float s = 0.f, ss = 0.f;
    for (int i = tid; i < M; i += 256) {
        int b = i / G;
        int g = i - b * G;
        float v = pool[((size_t)b * CO + ch) * G + g];
        s += v;
        ss += v * v;
    }
    __shared__ double sh[2][8];
    double rs = warp_sum_d((double)s);
    double rss = warp_sum_d((double)ss);
    if ((tid & 31) == 0) {
        sh[0][tid >> 5] = rs;
        sh[1][tid >> 5] = rss;
    }
    __syncthreads();
    __shared__ float sm, sr;
    if (tid == 0) {
        double t0 = 0, t1 = 0;
#pragma unroll
        for (int w = 0; w < 8; ++w) {
            t0 += sh[0][w];
            t1 += sh[1][w];
        }
        double mean = t0 / M;
        double var = t1 / M - mean * mean;
        sm = (float)mean;
        sr = rsqrtf((float)var + 1e-5f);
    }
    __syncthreads();
    float mean = sm, rstd = sr;
    float ga = gamma[ch], be = beta[ch];
    for (int i = tid; i < M; i += 256) {
        int b = i / G;
        int g = i - b * G;
        float v = pool[((size_t)b * CO + ch) * G + g];
        float y = (v - mean) * rstd * ga + be;
        float rr = 0.5f * y * (1.0f + erff(y * 0.70710678118654752440f));
        if (FOUT)
            out[((size_t)b * G + g) * CO + ch] = rr;   // feats layout for next stage
        else
            out[((size_t)b * CO + ch) * G + g] = rr;   // final [B,CO,G]
    }
}

// ---------------- launch ----------------
extern "C" void kernel_launch(void* const* d_in, const int* in_sizes, int n_in,
                              void* d_out, int out_size) {
    const float* xyz = (const float*)d_in[0];
    const float* x = (const float*)d_in[1];
    const float* B0 = (const float*)d_in[2];
    const float* B1 = (const float*)d_in[3];
    const float* ga0 = (const float*)d_in[4];
    const float* be0 = (const float*)d_in[5];
    const float* ga1 = (const float*)d_in[6];
    const float* be1 = (const float*)d_in[7];
    float* out = (float*)d_out;

    int *fpsP, *knnP;
    float *lc0P, *lc1P, *lcxP, *f0P, *f1P, *poolP;
    cudaGetSymbolAddress((void**)&fpsP, g_fps);
    cudaGetSymbolAddress((void**)&knnP, g_knn);
    cudaGetSymbolAddress((void**)&lc0P, g_lc0);
    cudaGetSymbolAddress((void**)&lc1P, g_lc1);
    cudaGetSymbolAddress((void**)&lcxP, g_lcx);
    cudaGetSymbolAddress((void**)&f0P, g_feats0);
    cudaGetSymbolAddress((void**)&f1P, g_feats1);
    cudaGetSymbolAddress((void**)&poolP, g_pool);

    // ---------------- stage 0: N=4096, G=2048, C=72 ----------------
    {
        constexpr int N = 4096, G = 2048, C = 72;
        int tt = BATCH * C * N;
        transpose_kernel<<<(tt + 255) / 256, 256>>>(x, f0P, C, N);
        fps_kernel<N, G><<<BATCH, 256>>>(xyz, fpsP);
        int gl = BATCH * G * (C + 3);
        gather_lc_kernel<N, G, C><<<(gl + 255) / 256, 256>>>(xyz, f0P, fpsP, lc0P, lcxP);
        knn_kernel<N, G><<<BATCH * G, 256>>>(xyz, lc0P, knnP);
        zero_acc_kernel<<<1, 32>>>();
        int P = BATCH * G * KNB;
        stats_kernel<N, G, C><<<(P + 255) / 256, 256>>>(xyz, f0P, knnP, lc0P, lcxP);
        finalize_kernel<<<1, 1>>>((double)BATCH * G * KNB * C,
                                  (double)BATCH * G * KNB * 3);
        main_kernel<N, G, C><<<BATCH * G, 160>>>(xyz, f0P, B0, knnP, lc0P, lcxP, poolP);
        bn_kernel<2 * C, G, true><<<2 * C, 256>>>(poolP, ga0, be0, f1P);
    }

    // ---------------- stage 1: N=2048, G=1024, C=144 ----------------
    {
        constexpr int N = 2048, G = 1024, C = 144;
        fps_kernel<N, G><<<BATCH, 256>>>(lc0P, fpsP);
        int gl = BATCH * G * (C + 3);
        gather_lc_kernel<N, G, C><<<(gl + 255) / 256, 256>>>(lc0P, f1P, fpsP, lc1P, lcxP);
        knn_kernel<N, G><<<BATCH * G, 256>>>(lc0P, lc1P, knnP);
        zero_acc_kernel<<<1, 32>>>();
        int P = BATCH * G * KNB;
        stats_kernel<N, G, C><<<(P + 255) / 256, 256>>>(lc0P, f1P, knnP, lc1P, lcxP);
        finalize_kernel<<<1, 1>>>((double)BATCH * G * KNB * C,
                                  (double)BATCH * G * KNB * 3);
        main_kernel<N, G, C><<<BATCH * G, 288>>>(lc0P, f1P, B1, knnP, lc1P, lcxP, poolP);
        bn_kernel<2 * C, G, false><<<2 * C, 256>>>(poolP, ga1, be1, out);
    }
    (void)in_sizes;
    (void)n_in;
    (void)out_size;
}

// round 5
// speedup vs baseline: 1.1551x; 1.1551x over previous
#include <cuda_runtime.h>
#include <math.h>

#define BATCH 4
#define KNB 24

// ---------------- scratch (device globals; no runtime allocation) ----------------
__device__ int    g_fps[BATCH * 2048];
__device__ int    g_knn[BATCH * 2048 * KNB];
__device__ float  g_lc0[BATCH * 2048 * 3];     // stage0 centers == stage1 xyz
__device__ float  g_lc1[BATCH * 1024 * 3];     // stage1 centers
__device__ float  g_lcx[BATCH * 2048 * 144];   // lc features
__device__ float  g_feats0[BATCH * 4096 * 72]; // x transposed to [B,N,C]
__device__ float  g_feats1[BATCH * 2048 * 144];// stage0 output in [B,N,C] layout
__device__ float  g_pool[BATCH * 144 * 2048];  // pooled [B,2C,G]
__device__ double g_acc[4];                    // s_x, ss_x, s_xyz, ss_xyz
__device__ float  g_inv[2];                    // 1/(std_x+1e-5), 1/(std_xyz+1e-5)

// ---------------- helpers ----------------
__device__ __forceinline__ double warp_sum_d(double v) {
#pragma unroll
    for (int off = 16; off > 0; off >>= 1)
        v += __shfl_down_sync(0xffffffffu, v, off);
    return v;
}

// ---------------- transpose [B,C,N] -> [B,N,C] ----------------
__global__ void transpose_kernel(const float* __restrict__ x, float* __restrict__ feats,
                                 int C, int N) {
    int i = blockIdx.x * blockDim.x + threadIdx.x;
    int total = BATCH * C * N;
    if (i >= total) return;
    int b = i / (C * N);
    int rr = i - b * (C * N);
    int c = rr / N;
    int n = rr - c * N;
    feats[((size_t)b * N + n) * C + c] = x[i];
}

// ---------------- furthest point sampling (exact ref arithmetic, first-max ties) ----
// One sync per iteration; packed u64 keys; writes center xyz directly.
template <int N, int G>
__global__ __launch_bounds__(256) void fps_kernel(const float* __restrict__ xyz,
                                                  int* __restrict__ out_idx,
                                                  float* __restrict__ out_lc) {
    constexpr int T = 256;
    constexpr int PPT = N / T;
    const int b = blockIdx.x;
    const int tid = threadIdx.x;
    const float* xb = xyz + (size_t)b * N * 3;

    float px[PPT], py[PPT], pz[PPT], dd[PPT];
#pragma unroll
    for (int i = 0; i < PPT; ++i) {
        int n = i * T + tid;                 // coalesced
        px[i] = xb[n * 3 + 0];
        py[i] = xb[n * 3 + 1];
        pz[i] = xb[n * 3 + 2];
        dd[i] = 1e10f;
    }
    __shared__ unsigned long long wb[2][8];

    int far = 0;
    for (int m = 0; m < G; ++m) {
        float cx = __ldg(xb + far * 3 + 0);
        float cy = __ldg(xb + far * 3 + 1);
        float cz = __ldg(xb + far * 3 + 2);
        if (tid == 0) {
            out_idx[(size_t)b * G + m] = far;
            float* o = out_lc + ((size_t)b * G + m) * 3;
            o[0] = cx; o[1] = cy; o[2] = cz;
        }
        float bv = -1.0f;
        int bi = 0;
#pragma unroll
        for (int i = 0; i < PPT; ++i) {
            float dx = __fsub_rn(px[i], cx);
            float dy = __fsub_rn(py[i], cy);
            float dz = __fsub_rn(pz[i], cz);
            float d = __fadd_rn(__fadd_rn(__fmul_rn(dx, dx), __fmul_rn(dy, dy)),
                                __fmul_rn(dz, dz));
            float nd = fminf(dd[i], d);
            dd[i] = nd;
            if (nd > bv) { bv = nd; bi = i * T + tid; }   // ascending n: first-max kept
        }
        // dist >= 0 so float bits are monotonic as unsigned. Max dist, tie -> min idx.
        unsigned long long key =
            ((unsigned long long)__float_as_uint(bv) << 32) | (unsigned)(N - 1 - bi);
#pragma unroll
        for (int off = 16; off > 0; off >>= 1) {
            unsigned long long o = __shfl_down_sync(0xffffffffu, key, off);
            if (o > key) key = o;
        }
        if ((tid & 31) == 0) wb[m & 1][tid >> 5] = key;
        __syncthreads();
        unsigned long long best = wb[m & 1][0];
#pragma unroll
        for (int w = 1; w < 8; ++w)
            if (wb[m & 1][w] > best) best = wb[m & 1][w];
        far = N - 1 - (int)(unsigned)(best & 0xffffffffu);
    }
}

// ---------------- gather center features ----------------
template <int N, int G, int C>
__global__ void gather_feat_kernel(const float* __restrict__ feats,
                                   const int* __restrict__ fps,
                                   float* __restrict__ lcx) {
    int i = blockIdx.x * blockDim.x + threadIdx.x;
    int total = BATCH * G * C;
    if (i >= total) return;
    int bg = i / C;
    int c = i - bg * C;
    int b = bg / G;
    int idx = fps[bg];
    lcx[(size_t)bg * C + c] = feats[((size_t)b * N + idx) * C + c];
}

// ---------------- kNN: conflict-free shared layout, one sync per pass ------------
template <int N, int G>
__global__ __launch_bounds__(256) void knn_kernel(const float* __restrict__ xyz,
                                                  const float* __restrict__ lc,
                                                  int* __restrict__ knn) {
    constexpr int T = 256;
    constexpr int PPT = N / T;
    const int bg = blockIdx.x;
    const int b = bg / G;
    const int tid = threadIdx.x;
    __shared__ float sd[N];
    __shared__ unsigned long long wb[2][8];
    const float* xb = xyz + (size_t)b * N * 3;
    float cx = lc[bg * 3 + 0], cy = lc[bg * 3 + 1], cz = lc[bg * 3 + 2];
    float sc = __fadd_rn(__fadd_rn(__fmul_rn(cx, cx), __fmul_rn(cy, cy)),
                         __fmul_rn(cz, cz));
#pragma unroll
    for (int i = 0; i < PPT; ++i) {
        int n = i * T + tid;                 // coalesced loads, conflict-free STS
        float xx = xb[n * 3 + 0], xy = xb[n * 3 + 1], xz = xb[n * 3 + 2];
        float sx = __fadd_rn(__fadd_rn(__fmul_rn(xx, xx), __fmul_rn(xy, xy)),
                             __fmul_rn(xz, xz));
        float dt = __fadd_rn(__fadd_rn(__fmul_rn(cx, xx), __fmul_rn(cy, xy)),
                             __fmul_rn(cz, xz));
        sd[n] = __fadd_rn(__fsub_rn(sc, __fmul_rn(2.0f, dt)), sx);
    }
    __syncthreads();
    const float INF = __int_as_float(0x7f800000);
    int prev = -1;
    for (int k = 0; k < KNB; ++k) {
        float bv = INF;
        int bi = N;
#pragma unroll
        for (int i = 0; i < PPT; ++i) {
            int n = i * T + tid;             // conflict-free LDS
            float v = sd[n];
            if (n != prev && v < bv) { bv = v; bi = n; }  // ascending n: first-min kept
        }
        // order-preserving flip handles possibly-negative distances
        unsigned fb = __float_as_uint(bv);
        fb ^= (fb & 0x80000000u) ? 0xFFFFFFFFu : 0x80000000u;
        unsigned long long key = ((unsigned long long)fb << 32) | (unsigned)bi;
#pragma unroll
        for (int off = 16; off > 0; off >>= 1) {
            unsigned long long o = __shfl_down_sync(0xffffffffu, key, off);
            if (o < key) key = o;
        }
        if ((tid & 31) == 0) wb[k & 1][tid >> 5] = key;
        __syncthreads();
        unsigned long long best = wb[k & 1][0];
#pragma unroll
        for (int w = 1; w < 8; ++w)
            if (wb[k & 1][w] < best) best = wb[k & 1][w];
        int win = (int)(unsigned)(best & 0xffffffffu);
        if (tid == 0) knn[(size_t)bg * KNB + k] = win;
        if ((win & (T - 1)) == tid) sd[win] = INF;  // owner pokes; others skip via prev
        prev = win;
    }
}

// ---------------- global std statistics ----------------
__global__ void zero_acc_kernel() {
    if (threadIdx.x < 4) g_acc[threadIdx.x] = 0.0;
}

template <int N, int G, int C>
__global__ __launch_bounds__(256) void stats_kernel(const float* __restrict__ xyz,
                                                    const float* __restrict__ feats,
                                                    const int* __restrict__ knn,
                                                    const float* __restrict__ lcxyz,
                                                    const float* __restrict__ lcx) {
    const int P = BATCH * G * KNB;
    int p = blockIdx.x * blockDim.x + threadIdx.x;
    float s1 = 0.f, ss1 = 0.f, s2 = 0.f, ss2 = 0.f;
    if (p < P) {
        int b = p / (G * KNB);
        int rg = p - b * (G * KNB);
        int g = rg / KNB;
        int bg = b * G + g;
        int kidx = knn[p];
        const float* kp = xyz + ((size_t)b * N + kidx) * 3;
        const float* lp = lcxyz + (size_t)bg * 3;
#pragma unroll
        for (int j = 0; j < 3; ++j) {
            float d = kp[j] - lp[j];
            s2 += d;
            ss2 += d * d;
        }
        const float4* kf = (const float4*)(feats + ((size_t)b * N + kidx) * C);
        const float4* lf = (const float4*)(lcx + (size_t)bg * C);
#pragma unroll 4
        for (int c = 0; c < C / 4; ++c) {
            float4 a = kf[c], l = lf[c];
            float d0 = a.x - l.x, d1 = a.y - l.y, d2 = a.z - l.z, d3 = a.w - l.w;
            s1 += d0; ss1 += d0 * d0;
            s1 += d1; ss1 += d1 * d1;
            s1 += d2; ss1 += d2 * d2;
            s1 += d3; ss1 += d3 * d3;
        }
    }
    __shared__ double sh[4][8];
    double v[4] = {(double)s1, (double)ss1, (double)s2, (double)ss2};
#pragma unroll
    for (int q = 0; q < 4; ++q) {
        double r = warp_sum_d(v[q]);
        if ((threadIdx.x & 31) == 0) sh[q][threadIdx.x >> 5] = r;
    }
    __syncthreads();
    if (threadIdx.x == 0) {
#pragma unroll
        for (int q = 0; q < 4; ++q) {
            double t = 0;
#pragma unroll
            for (int w = 0; w < 8; ++w) t += sh[q][w];
            atomicAdd(&g_acc[q], t);
        }
    }
}

__global__ void finalize_kernel(double n1, double n2) {
    double v1 = (g_acc[1] - g_acc[0] * g_acc[0] / n1) / (n1 - 1.0);
    double v2 = (g_acc[3] - g_acc[2] * g_acc[2] / n2) / (n2 - 1.0);
    g_inv[0] = 1.0f / ((float)sqrt(v1) + 1e-5f);
    g_inv[1] = 1.0f / ((float)sqrt(v2) + 1e-5f);
}

// ---------------- fused LGA + pooling: 1 thread per output channel ---------------
// pooled[b,ch,g] = k_anp(w)+mean_K(w) = 2*mean_K(w)  (k_anp is identity-mean)
template <int N, int G, int C>
__global__ void main_kernel(const float* __restrict__ xyz, const float* __restrict__ feats,
                            const float* __restrict__ Bmat, const int* __restrict__ knn,
                            const float* __restrict__ lcxyz, const float* __restrict__ lcx,
                            float* __restrict__ pool) {
    constexpr int C2 = 2 * C;
    constexpr int F = C / 3;   // my_dim/(2*3)
    constexpr int CH = C / 2;
    __shared__ float sg[KNB][8];   // nx,ny,nz,crx,cry,crz,dt
    __shared__ int skidx[KNB];
    const int bg = blockIdx.x;
    const int b = bg / G;
    const int g = bg - b * G;
    const int ch = threadIdx.x;

    const float lx = lcxyz[bg * 3 + 0];
    const float ly = lcxyz[bg * 3 + 1];
    const float lz = lcxyz[bg * 3 + 2];
    const float inv_x = g_inv[0];
    const float inv_p = g_inv[1];

    if (ch < KNB) {
        int kidx = knn[(size_t)bg * KNB + ch];
        skidx[ch] = kidx;
        const float* kp = xyz + ((size_t)b * N + kidx) * 3;
        float nx = (kp[0] - lx) * inv_p;
        float ny = (kp[1] - ly) * inv_p;
        float nz = (kp[2] - lz) * inv_p;
        sg[ch][0] = nx;
        sg[ch][1] = ny;
        sg[ch][2] = nz;
        sg[ch][3] = ny * lz - nz * ly;
        sg[ch][4] = nz * lx - nx * lz;
        sg[ch][5] = nx * ly - ny * lx;
        sg[ch][6] = nx * lx + ny * ly + nz * lz;
    }
    __syncthreads();
    if (ch >= C2) return;

    const int c3 = ch / (2 * F);
    const int r = ch - c3 * (2 * F);
    const int f = r >> 1;
    const int s = r & 1;
    const float de = powf(100.0f, (float)f / (float)F);
    const float lcv = (c3 == 0) ? lx : ((c3 == 1) ? ly : lz);
    const float divL = 1000.0f * lcv / de;
    const float peL = s ? cosf(divL) : sinf(divL);
    const float scl = 1000.0f / de;

    const bool isFourier = (ch >= C);
    float lcf = 0.0f;
    float B0c = 0, B1c = 0, B2c = 0, B3c = 0, B4c = 0, B5c = 0, B6c = 0;
    bool isSin = false;
    if (!isFourier) {
        lcf = lcx[(size_t)bg * C + ch];
    } else {
        int jj = ch - C;
        isSin = (jj < CH);
        int j = isSin ? jj : (jj - CH);
        B0c = Bmat[0 * CH + j];
        B1c = Bmat[1 * CH + j];
        B2c = Bmat[2 * CH + j];
        B3c = Bmat[3 * CH + j];
        B4c = Bmat[4 * CH + j];
        B5c = Bmat[5 * CH + j];
        B6c = Bmat[6 * CH + j];
    }
    float acc = 0.0f;
#pragma unroll 1
    for (int k = 0; k < KNB; ++k) {
        float nc = sg[k][c3];
        float divK = scl * nc;
        float pe = (s ? cosf(divK) : sinf(divK)) + peL;
        float a;
        if (!isFourier) {
            a = (feats[((size_t)b * N + skidx[k]) * C + ch] - lcf) * inv_x;
        } else {
            float proj = B0c * sg[k][0] + B1c * sg[k][1] + B2c * sg[k][2] +
                         B3c * sg[k][3] + B4c * sg[k][4] + B5c * sg[k][5] +
                         B6c * sg[k][6];
            proj *= 6.283185307179586f;
            float t = isSin ? sinf(proj) : cosf(proj);
            float t2 = t * t;
            a = t * t2 * t2;   // sign(t)*|t|^5
        }
        acc += (a + pe) * pe;
    }
    float mval = acc * (1.0f / 24.0f);
    pool[((size_t)b * C2 + ch) * G + g] = mval + mval;
}

// ---------------- BatchNorm (training-mode batch stats) + exact GELU --------------
template <int CO, int G, bool FOUT>
__global__ __launch_bounds__(256) void bn_kernel(const float* __restrict__ pool,
                                                 const float* __restrict__ gamma,
                                                 const float* __restrict__ beta,
                                                 float* __restrict__ out) {
    const int ch = blockIdx.x;
    const int tid = threadIdx.x;
    const int M = BATCH * G;
    float s = 0.f, ss = 0.f;
    for (int i = tid; i < M; i += 256) {
        int b = i / G;
        int g = i - b * G;
        float v = pool[((size_t)b * CO + ch) * G + g];
        s += v;
        ss += v * v;
    }
    __shared__ double sh[2][8];
    double rs = warp_sum_d((double)s);
    double rss = warp_sum_d((double)ss);
    if ((tid & 31) == 0) {
        sh[0][tid >> 5] = rs;
        sh[1][tid >> 5] = rss;
    }
    __syncthreads();
    __shared__ float sm, sr;
    if (tid == 0) {
        double t0 = 0, t1 = 0;
#pragma unroll
        for (int w = 0; w < 8; ++w) {
            t0 += sh[0][w];
            t1 += sh[1][w];
        }
        double mean = t0 / M;
        double var = t1 / M - mean * mean;
        sm = (float)mean;
        sr = rsqrtf((float)var + 1e-5f);
    }
    __syncthreads();
    float mean = sm, rstd = sr;
    float ga = gamma[ch], be = beta[ch];
    for (int i = tid; i < M; i += 256) {
        int b = i / G;
        int g = i - b * G;
        float v = pool[((size_t)b * CO + ch) * G + g];
        float y = (v - mean) * rstd * ga + be;
        float rr = 0.5f * y * (1.0f + erff(y * 0.70710678118654752440f));
        if (FOUT)
            out[((size_t)b * G + g) * CO + ch] = rr;   // feats layout for next stage
        else
            out[((size_t)b * CO + ch) * G + g] = rr;   // final [B,CO,G]
    }
}

// ---------------- launch ----------------
extern "C" void kernel_launch(void* const* d_in, const int* in_sizes, int n_in,
                              void* d_out, int out_size) {
    const float* xyz = (const float*)d_in[0];
    const float* x = (const float*)d_in[1];
    const float* B0 = (const float*)d_in[2];
    const float* B1 = (const float*)d_in[3];
    const float* ga0 = (const float*)d_in[4];
    const float* be0 = (const float*)d_in[5];
    const float* ga1 = (const float*)d_in[6];
    const float* be1 = (const float*)d_in[7];
    float* out = (float*)d_out;

    int *fpsP, *knnP;
    float *lc0P, *lc1P, *lcxP, *f0P, *f1P, *poolP;
    cudaGetSymbolAddress((void**)&fpsP, g_fps);
    cudaGetSymbolAddress((void**)&knnP, g_knn);
    cudaGetSymbolAddress((void**)&lc0P, g_lc0);
    cudaGetSymbolAddress((void**)&lc1P, g_lc1);
    cudaGetSymbolAddress((void**)&lcxP, g_lcx);
    cudaGetSymbolAddress((void**)&f0P, g_feats0);
    cudaGetSymbolAddress((void**)&f1P, g_feats1);
    cudaGetSymbolAddress((void**)&poolP, g_pool);

    // ---------------- stage 0: N=4096, G=2048, C=72 ----------------
    {
        constexpr int N = 4096, G = 2048, C = 72;
        int tt = BATCH * C * N;
        transpose_kernel<<<(tt + 255) / 256, 256>>>(x, f0P, C, N);
        fps_kernel<N, G><<<BATCH, 256>>>(xyz, fpsP, lc0P);
        int gl = BATCH * G * C;
        gather_feat_kernel<N, G, C><<<(gl + 255) / 256, 256>>>(f0P, fpsP, lcxP);
        knn_kernel<N, G><<<BATCH * G, 256>>>(xyz, lc0P, knnP);
        zero_acc_kernel<<<1, 32>>>();
        int P = BATCH * G * KNB;
        stats_kernel<N, G, C><<<(P + 255) / 256, 256>>>(xyz, f0P, knnP, lc0P, lcxP);
        finalize_kernel<<<1, 1>>>((double)BATCH * G * KNB * C,
                                  (double)BATCH * G * KNB * 3);
        main_kernel<N, G, C><<<BATCH * G, 160>>>(xyz, f0P, B0, knnP, lc0P, lcxP, poolP);
        bn_kernel<2 * C, G, true><<<2 * C, 256>>>(poolP, ga0, be0, f1P);
    }

    // ---------------- stage 1: N=2048, G=1024, C=144 ----------------
    {
        constexpr int N = 2048, G = 1024, C = 144;
        fps_kernel<N, G><<<BATCH, 256>>>(lc0P, fpsP, lc1P);
        int gl = BATCH * G * C;
        gather_feat_kernel<N, G, C><<<(gl + 255) / 256, 256>>>(f1P, fpsP, lcxP);
        knn_kernel<N, G><<<BATCH * G, 256>>>(lc0P, lc1P, knnP);
        zero_acc_kernel<<<1, 32>>>();
        int P = BATCH * G * KNB;
        stats_kernel<N, G, C><<<(P + 255) / 256, 256>>>(lc0P, f1P, knnP, lc1P, lcxP);
        finalize_kernel<<<1, 1>>>((double)BATCH * G * KNB * C,
                                  (double)BATCH * G * KNB * 3);
        main_kernel<N, G, C><<<BATCH * G, 288>>>(lc0P, f1P, B1, knnP, lc1P, lcxP, poolP);
        bn_kernel<2 * C, G, false><<<2 * C, 256>>>(poolP, ga1, be1, out);
    }
    (void)in_sizes;
    (void)n_in;
    (void)out_size;
}

// round 8
// speedup vs baseline: 1.3498x; 1.1685x over previous
#include <cuda_runtime.h>
#include <math.h>

#define BATCH 4
#define KNB 24

// ---------------- scratch (device globals; no runtime allocation) ----------------
__device__ int    g_fps[BATCH * 2048];
__device__ int    g_knn[BATCH * 2048 * KNB];
__device__ float  g_lc0[BATCH * 2048 * 3];     // stage0 centers == stage1 xyz
__device__ float  g_lc1[BATCH * 1024 * 3];     // stage1 centers
__device__ float  g_lcx[BATCH * 2048 * 144];   // lc features
__device__ float  g_feats0[BATCH * 4096 * 72]; // x transposed to [B,N,C]
__device__ float  g_feats1[BATCH * 2048 * 144];// stage0 output in [B,N,C] layout
__device__ float  g_pool[BATCH * 144 * 2048];  // pooled [B,2C,G]
__device__ double g_acc[4];                    // s_x, ss_x, s_xyz, ss_xyz
__device__ float  g_inv[2];                    // 1/(std_x+1e-5), 1/(std_xyz+1e-5)

// ---------------- helpers ----------------
__device__ __forceinline__ double warp_sum_d(double v) {
#pragma unroll
    for (int off = 16; off > 0; off >>= 1)
        v += __shfl_down_sync(0xffffffffu, v, off);
    return v;
}

// ---------------- transpose [B,C,N] -> [B,N,C] ----------------
__global__ void transpose_kernel(const float* __restrict__ x, float* __restrict__ feats,
                                 int C, int N) {
    int i = blockIdx.x * blockDim.x + threadIdx.x;
    int total = BATCH * C * N;
    if (i >= total) return;
    int b = i / (C * N);
    int rr = i - b * (C * N);
    int c = rr / N;
    int n = rr - c * N;
    feats[((size_t)b * N + n) * C + c] = x[i];
}

// ---------------- furthest point sampling (exact ref arithmetic, first-max ties) ----
// One sync per iteration; packed u64 keys; writes center xyz directly.
template <int N, int G>
__global__ __launch_bounds__(256) void fps_kernel(const float* __restrict__ xyz,
                                                  int* __restrict__ out_idx,
                                                  float* __restrict__ out_lc) {
    constexpr int T = 256;
    constexpr int PPT = N / T;
    const int b = blockIdx.x;
    const int tid = threadIdx.x;
    const float* xb = xyz + (size_t)b * N * 3;

    float px[PPT], py[PPT], pz[PPT], dd[PPT];
#pragma unroll
    for (int i = 0; i < PPT; ++i) {
        int n = i * T + tid;                 // coalesced
        px[i] = xb[n * 3 + 0];
        py[i] = xb[n * 3 + 1];
        pz[i] = xb[n * 3 + 2];
        dd[i] = 1e10f;
    }
    __shared__ unsigned long long wb[2][8];

    int far = 0;
    for (int m = 0; m < G; ++m) {
        float cx = __ldg(xb + far * 3 + 0);
        float cy = __ldg(xb + far * 3 + 1);
        float cz = __ldg(xb + far * 3 + 2);
        if (tid == 0) {
            out_idx[(size_t)b * G + m] = far;
            float* o = out_lc + ((size_t)b * G + m) * 3;
            o[0] = cx; o[1] = cy; o[2] = cz;
        }
        float bv = -1.0f;
        int bi = 0;
#pragma unroll
        for (int i = 0; i < PPT; ++i) {
            float dx = __fsub_rn(px[i], cx);
            float dy = __fsub_rn(py[i], cy);
            float dz = __fsub_rn(pz[i], cz);
            float d = __fadd_rn(__fadd_rn(__fmul_rn(dx, dx), __fmul_rn(dy, dy)),
                                __fmul_rn(dz, dz));
            float nd = fminf(dd[i], d);
            dd[i] = nd;
            if (nd > bv) { bv = nd; bi = i * T + tid; }   // ascending n: first-max kept
        }
        // dist >= 0 so float bits are monotonic as unsigned. Max dist, tie -> min idx.
        unsigned long long key =
            ((unsigned long long)__float_as_uint(bv) << 32) | (unsigned)(N - 1 - bi);
#pragma unroll
        for (int off = 16; off > 0; off >>= 1) {
            unsigned long long o = __shfl_down_sync(0xffffffffu, key, off);
            if (o > key) key = o;
        }
        if ((tid & 31) == 0) wb[m & 1][tid >> 5] = key;
        __syncthreads();
        unsigned long long best = wb[m & 1][0];
#pragma unroll
        for (int w = 1; w < 8; ++w)
            if (wb[m & 1][w] > best) best = wb[m & 1][w];
        far = N - 1 - (int)(unsigned)(best & 0xffffffffu);
    }
}

// ---------------- gather center features ----------------
template <int N, int G, int C>
__global__ void gather_feat_kernel(const float* __restrict__ feats,
                                   const int* __restrict__ fps,
                                   float* __restrict__ lcx) {
    int i = blockIdx.x * blockDim.x + threadIdx.x;
    int total = BATCH * G * C;
    if (i >= total) return;
    int bg = i / C;
    int c = i - bg * C;
    int b = bg / G;
    int idx = fps[bg];
    lcx[(size_t)bg * C + c] = feats[((size_t)b * N + idx) * C + c];
}

// ---------------- kNN: cached-register local min; only winner rescans ------------
// Selection math/keys identical to repeated stable argmin (lowest-index ties).
template <int N, int G>
__global__ __launch_bounds__(256) void knn_kernel(const float* __restrict__ xyz,
                                                  const float* __restrict__ lc,
                                                  int* __restrict__ knn) {
    constexpr int T = 256;
    constexpr int PPT = N / T;
    const int bg = blockIdx.x;
    const int b = bg / G;
    const int tid = threadIdx.x;
    __shared__ float sd[N];
    __shared__ unsigned long long wb[2][8];
    const float* xb = xyz + (size_t)b * N * 3;
    float cx = lc[bg * 3 + 0], cy = lc[bg * 3 + 1], cz = lc[bg * 3 + 2];
    float sc = __fadd_rn(__fadd_rn(__fmul_rn(cx, cx), __fmul_rn(cy, cy)),
                         __fmul_rn(cz, cz));
    float bv = __int_as_float(0x7f800000);
    int bi = N;
#pragma unroll
    for (int i = 0; i < PPT; ++i) {
        int n = i * T + tid;                 // coalesced loads, conflict-free STS
        float xx = xb[n * 3 + 0], xy = xb[n * 3 + 1], xz = xb[n * 3 + 2];
        float sx = __fadd_rn(__fadd_rn(__fmul_rn(xx, xx), __fmul_rn(xy, xy)),
                             __fmul_rn(xz, xz));
        float dt = __fadd_rn(__fadd_rn(__fmul_rn(cx, xx), __fmul_rn(cy, xy)),
                             __fmul_rn(cz, xz));
        float d = __fadd_rn(__fsub_rn(sc, __fmul_rn(2.0f, dt)), sx);
        sd[n] = d;
        if (d < bv) { bv = d; bi = n; }      // ascending n: first-min kept
    }
    // order-preserving flip (handles possibly-negative distances)
    unsigned fb = __float_as_uint(bv);
    fb ^= (fb & 0x80000000u) ? 0xFFFFFFFFu : 0x80000000u;
    unsigned long long key = ((unsigned long long)fb << 32) | (unsigned)bi;
    __syncthreads();                          // sd visible to owner rescans

    const float INF = __int_as_float(0x7f800000);
    for (int k = 0; k < KNB; ++k) {
        unsigned long long kk = key;
#pragma unroll
        for (int off = 16; off > 0; off >>= 1) {
            unsigned long long o = __shfl_down_sync(0xffffffffu, kk, off);
            if (o < kk) kk = o;
        }
        if ((tid & 31) == 0) wb[k & 1][tid >> 5] = kk;
        __syncthreads();
        unsigned long long best = wb[k & 1][0];
#pragma unroll
        for (int w = 1; w < 8; ++w)
            if (wb[k & 1][w] < best) best = wb[k & 1][w];
        int win = (int)(unsigned)(best & 0xffffffffu);
        if (tid == 0) knn[(size_t)bg * KNB + k] = win;
        if ((win & (T - 1)) == tid) {
            // I own the winner: poke it out and recompute my cached min.
            sd[win] = INF;
            float nbv = INF;
            int nbi = N;
#pragma unroll
            for (int i = 0; i < PPT; ++i) {
                int n = i * T + tid;
                float v = sd[n];
                if (v < nbv) { nbv = v; nbi = n; }
            }
            unsigned nfb = __float_as_uint(nbv);
            nfb ^= (nfb & 0x80000000u) ? 0xFFFFFFFFu : 0x80000000u;
            key = ((unsigned long long)nfb << 32) | (unsigned)nbi;
        }
    }
}

// ---------------- global std statistics ----------------
__global__ void zero_acc_kernel() {
    if (threadIdx.x < 4) g_acc[threadIdx.x] = 0.0;
}

template <int N, int G, int C>
__global__ __launch_bounds__(256) void stats_kernel(const float* __restrict__ xyz,
                                                    const float* __restrict__ feats,
                                                    const int* __restrict__ knn,
                                                    const float* __restrict__ lcxyz,
                                                    const float* __restrict__ lcx) {
    const int P = BATCH * G * KNB;
    int p = blockIdx.x * blockDim.x + threadIdx.x;
    float s1 = 0.f, ss1 = 0.f, s2 = 0.f, ss2 = 0.f;
    if (p < P) {
        int b = p / (G * KNB);
        int rg = p - b * (G * KNB);
        int g = rg / KNB;
        int bg = b * G + g;
        int kidx = knn[p];
        const float* kp = xyz + ((size_t)b * N + kidx) * 3;
        const float* lp = lcxyz + (size_t)bg * 3;
#pragma unroll
        for (int j = 0; j < 3; ++j) {
            float d = kp[j] - lp[j];
            s2 += d;
            ss2 += d * d;
        }
        const float4* kf = (const float4*)(feats + ((size_t)b * N + kidx) * C);
        const float4* lf = (const float4*)(lcx + (size_t)bg * C);
#pragma unroll 4
        for (int c = 0; c < C / 4; ++c) {
            float4 a = kf[c], l = lf[c];
            float d0 = a.x - l.x, d1 = a.y - l.y, d2 = a.z - l.z, d3 = a.w - l.w;
            s1 += d0; ss1 += d0 * d0;
            s1 += d1; ss1 += d1 * d1;
            s1 += d2; ss1 += d2 * d2;
            s1 += d3; ss1 += d3 * d3;
        }
    }
    __shared__ double sh[4][8];
    double v[4] = {(double)s1, (double)ss1, (double)s2, (double)ss2};
#pragma unroll
    for (int q = 0; q < 4; ++q) {
        double r = warp_sum_d(v[q]);
        if ((threadIdx.x & 31) == 0) sh[q][threadIdx.x >> 5] = r;
    }
    __syncthreads();
    if (threadIdx.x == 0) {
#pragma unroll
        for (int q = 0; q < 4; ++q) {
            double t = 0;
#pragma unroll
            for (int w = 0; w < 8; ++w) t += sh[q][w];
            atomicAdd(&g_acc[q], t);
        }
    }
}

__global__ void finalize_kernel(double n1, double n2) {
    double v1 = (g_acc[1] - g_acc[0] * g_acc[0] / n1) / (n1 - 1.0);
    double v2 = (g_acc[3] - g_acc[2] * g_acc[2] / n2) / (n2 - 1.0);
    g_inv[0] = 1.0f / ((float)sqrt(v1) + 1e-5f);
    g_inv[1] = 1.0f / ((float)sqrt(v2) + 1e-5f);
}

// ---------------- fused LGA + pooling: 1 thread per output channel ---------------
// pooled[b,ch,g] = k_anp(w)+mean_K(w) = 2*mean_K(w)  (k_anp is identity-mean)
template <int N, int G, int C>
__global__ void main_kernel(const float* __restrict__ xyz, const float* __restrict__ feats,
                            const float* __restrict__ Bmat, const int* __restrict__ knn,
                            const float* __restrict__ lcxyz, const float* __restrict__ lcx,
                            float* __restrict__ pool) {
    constexpr int C2 = 2 * C;
    constexpr int F = C / 3;   // my_dim/(2*3)
    constexpr int CH = C / 2;
    __shared__ float sg[KNB][8];   // nx,ny,nz,crx,cry,crz,dt
    __shared__ int skidx[KNB];
    const int bg = blockIdx.x;
    const int b = bg / G;
    const int g = bg - b * G;
    const int ch = threadIdx.x;

    const float lx = lcxyz[bg * 3 + 0];
    const float ly = lcxyz[bg * 3 + 1];
    const float lz = lcxyz[bg * 3 + 2];
    const float inv_x = g_inv[0];
    const float inv_p = g_inv[1];

    if (ch < KNB) {
        int kidx = knn[(size_t)bg * KNB + ch];
        skidx[ch] = kidx;
        const float* kp = xyz + ((size_t)b * N + kidx) * 3;
        float nx = (kp[0] - lx) * inv_p;
        float ny = (kp[1] - ly) * inv_p;
        float nz = (kp[2] - lz) * inv_p;
        sg[ch][0] = nx;
        sg[ch][1] = ny;
        sg[ch][2] = nz;
        sg[ch][3] = ny * lz - nz * ly;
        sg[ch][4] = nz * lx - nx * lz;
        sg[ch][5] = nx * ly - ny * lx;
        sg[ch][6] = nx * lx + ny * ly + nz * lz;
    }
    __syncthreads();
    if (ch >= C2) return;

    const int c3 = ch / (2 * F);
    const int r = ch - c3 * (2 * F);
    const int f = r >> 1;
    const int s = r & 1;
    const float de = powf(100.0f, (float)f / (float)F);
    const float lcv = (c3 == 0) ? lx : ((c3 == 1) ? ly : lz);
    const float divL = 1000.0f * lcv / de;
    const float peL = s ? cosf(divL) : sinf(divL);
    const float scl = 1000.0f / de;

    const bool isFourier = (ch >= C);
    float lcf = 0.0f;
    float B0c = 0, B1c = 0, B2c = 0, B3c = 0, B4c = 0, B5c = 0, B6c = 0;
    bool isSin = false;
    if (!isFourier) {
        lcf = lcx[(size_t)bg * C + ch];
    } else {
        int jj = ch - C;
        isSin = (jj < CH);
        int j = isSin ? jj : (jj - CH);
        B0c = Bmat[0 * CH + j];
        B1c = Bmat[1 * CH + j];
        B2c = Bmat[2 * CH + j];
        B3c = Bmat[3 * CH + j];
        B4c = Bmat[4 * CH + j];
        B5c = Bmat[5 * CH + j];
        B6c = Bmat[6 * CH + j];
    }
    float acc = 0.0f;
#pragma unroll 1
    for (int k = 0; k < KNB; ++k) {
        float nc = sg[k][c3];
        float divK = scl * nc;
        float pe = (s ? cosf(divK) : sinf(divK)) + peL;
        float a;
        if (!isFourier) {
            a = (feats[((size_t)b * N + skidx[k]) * C + ch] - lcf) * inv_x;
        } else {
            float proj = B0c * sg[k][0] + B1c * sg[k][1] + B2c * sg[k][2] +
                         B3c * sg[k][3] + B4c * sg[k][4] + B5c * sg[k][5] +
                         B6c * sg[k][6];
            proj *= 6.283185307179586f;
            float t = isSin ? sinf(proj) : cosf(proj);
            float t2 = t * t;
            a = t * t2 * t2;   // sign(t)*|t|^5
        }
        acc += (a + pe) * pe;
    }
    float mval = acc * (1.0f / 24.0f);
    pool[((size_t)b * C2 + ch) * G + g] = mval + mval;
}

// ---------------- BatchNorm (training-mode batch stats) + exact GELU --------------
template <int CO, int G, bool FOUT>
__global__ __launch_bounds__(256) void bn_kernel(const float* __restrict__ pool,
                                                 const float* __restrict__ gamma,
                                                 const float* __restrict__ beta,
                                                 float* __restrict__ out) {
    const int ch = blockIdx.x;
    const int tid = threadIdx.x;
    const int M = BATCH * G;
    float s = 0.f, ss = 0.f;
    for (int i = tid; i < M; i += 256) {
        int b = i / G;
        int g = i - b * G;
        float v = pool[((size_t)b * CO + ch) * G + g];
        s += v;
        ss += v * v;
    }
    __shared__ double sh[2][8];
    double rs = warp_sum_d((double)s);
    double rss = warp_sum_d((double)ss);
    if ((tid & 31) == 0) {
        sh[0][tid >> 5] = rs;
        sh[1][tid >> 5] = rss;
    }
    __syncthreads();
    __shared__ float sm, sr;
    if (tid == 0) {
        double t0 = 0, t1 = 0;
#pragma unroll
        for (int w = 0; w < 8; ++w) {
            t0 += sh[0][w];
            t1 += sh[1][w];
        }
        double mean = t0 / M;
        double var = t1 / M - mean * mean;
        sm = (float)mean;
        sr = rsqrtf((float)var + 1e-5f);
    }
    __syncthreads();
    float mean = sm, rstd = sr;
    float ga = gamma[ch], be = beta[ch];
    for (int i = tid; i < M; i += 256) {
        int b = i / G;
        int g = i - b * G;
        float v = pool[((size_t)b * CO + ch) * G + g];
        float y = (v - mean) * rstd * ga + be;
        float rr = 0.5f * y * (1.0f + erff(y * 0.70710678118654752440f));
        if (FOUT)
            out[((size_t)b * G + g) * CO + ch] = rr;   // feats layout for next stage
        else
            out[((size_t)b * CO + ch) * G + g] = rr;   // final [B,CO,G]
    }
}

// ---------------- launch ----------------
extern "C" void kernel_launch(void* const* d_in, const int* in_sizes, int n_in,
                              void* d_out, int out_size) {
    const float* xyz = (const float*)d_in[0];
    const float* x = (const float*)d_in[1];
    const float* B0 = (const float*)d_in[2];
    const float* B1 = (const float*)d_in[3];
    const float* ga0 = (const float*)d_in[4];
    const float* be0 = (const float*)d_in[5];
    const float* ga1 = (const float*)d_in[6];
    const float* be1 = (const float*)d_in[7];
    float* out = (float*)d_out;

    int *fpsP, *knnP;
    float *lc0P, *lc1P, *lcxP, *f0P, *f1P, *poolP;
    cudaGetSymbolAddress((void**)&fpsP, g_fps);
    cudaGetSymbolAddress((void**)&knnP, g_knn);
    cudaGetSymbolAddress((void**)&lc0P, g_lc0);
    cudaGetSymbolAddress((void**)&lc1P, g_lc1);
    cudaGetSymbolAddress((void**)&lcxP, g_lcx);
    cudaGetSymbolAddress((void**)&f0P, g_feats0);
    cudaGetSymbolAddress((void**)&f1P, g_feats1);
    cudaGetSymbolAddress((void**)&poolP, g_pool);

    // ---------------- stage 0: N=4096, G=2048, C=72 ----------------
    {
        constexpr int N = 4096, G = 2048, C = 72;
        int tt = BATCH * C * N;
        transpose_kernel<<<(tt + 255) / 256, 256>>>(x, f0P, C, N);
        fps_kernel<N, G><<<BATCH, 256>>>(xyz, fpsP, lc0P);
        int gl = BATCH * G * C;
        gather_feat_kernel<N, G, C><<<(gl + 255) / 256, 256>>>(f0P, fpsP, lcxP);
        knn_kernel<N, G><<<BATCH * G, 256>>>(xyz, lc0P, knnP);
        zero_acc_kernel<<<1, 32>>>();
        int P = BATCH * G * KNB;
        stats_kernel<N, G, C><<<(P + 255) / 256, 256>>>(xyz, f0P, knnP, lc0P, lcxP);
        finalize_kernel<<<1, 1>>>((double)BATCH * G * KNB * C,
                                  (double)BATCH * G * KNB * 3);
        main_kernel<N, G, C><<<BATCH * G, 160>>>(xyz, f0P, B0, knnP, lc0P, lcxP, poolP);
        bn_kernel<2 * C, G, true><<<2 * C, 256>>>(poolP, ga0, be0, f1P);
    }

    // ---------------- stage 1: N=2048, G=1024, C=144 ----------------
    {
        constexpr int N = 2048, G = 1024, C = 144;
        fps_kernel<N, G><<<BATCH, 256>>>(lc0P, fpsP, lc1P);
        int gl = BATCH * G * C;
        gather_feat_kernel<N, G, C><<<(gl + 255) / 256, 256>>>(f1P, fpsP, lcxP);
        knn_kernel<N, G><<<BATCH * G, 256>>>(lc0P, lc1P, knnP);
        zero_acc_kernel<<<1, 32>>>();
        int P = BATCH * G * KNB;
        stats_kernel<N, G, C><<<(P + 255) / 256, 256>>>(lc0P, f1P, knnP, lc1P, lcxP);
        finalize_kernel<<<1, 1>>>((double)BATCH * G * KNB * C,
                                  (double)BATCH * G * KNB * 3);
        main_kernel<N, G, C><<<BATCH * G, 288>>>(lc0P, f1P, B1, knnP, lc1P, lcxP, poolP);
        bn_kernel<2 * C, G, false><<<2 * C, 256>>>(poolP, ga1, be1, out);
    }
    (void)in_sizes;
    (void)n_in;
    (void)out_size;
}

// round 10
// speedup vs baseline: 1.4651x; 1.0854x over previous
#include <cuda_runtime.h>
#include <math.h>

#define BATCH 4
#define KNB 24

// ---------------- scratch (device globals; no runtime allocation) ----------------
// Stage-separated buffers so stream B (fps0->fps1->knn1) never aliases stream A work.
__device__ int    g_fps0[BATCH * 2048];
__device__ int    g_fps1[BATCH * 1024];
__device__ int    g_knn0[BATCH * 2048 * KNB];
__device__ int    g_knn1[BATCH * 1024 * KNB];
__device__ float  g_lc0[BATCH * 2048 * 3];     // stage0 centers == stage1 xyz
__device__ float  g_lc1[BATCH * 1024 * 3];     // stage1 centers
__device__ float  g_lcx0[BATCH * 2048 * 72];   // stage0 center features
__device__ float  g_lcx1[BATCH * 1024 * 144];  // stage1 center features
__device__ float  g_feats0[BATCH * 4096 * 72]; // x transposed to [B,N,C]
__device__ float  g_feats1[BATCH * 2048 * 144];// stage0 output in [B,N,C] layout
__device__ float  g_pool0[BATCH * 144 * 2048];
__device__ float  g_pool1[BATCH * 288 * 1024];
__device__ double g_acc0[4];
__device__ double g_acc1[4];
__device__ float  g_inv0[2];
__device__ float  g_inv1[2];

// ---------------- helpers ----------------
__device__ __forceinline__ double warp_sum_d(double v) {
#pragma unroll
    for (int off = 16; off > 0; off >>= 1)
        v += __shfl_down_sync(0xffffffffu, v, off);
    return v;
}

// ---------------- transpose [B,C,N] -> [B,N,C] ----------------
__global__ void transpose_kernel(const float* __restrict__ x, float* __restrict__ feats,
                                 int C, int N) {
    int i = blockIdx.x * blockDim.x + threadIdx.x;
    int total = BATCH * C * N;
    if (i >= total) return;
    int b = i / (C * N);
    int rr = i - b * (C * N);
    int c = rr / N;
    int n = rr - c * N;
    feats[((size_t)b * N + n) * C + c] = x[i];
}

// ---------------- furthest point sampling (exact ref arithmetic, first-max ties) ----
template <int N, int G>
__global__ __launch_bounds__(256) void fps_kernel(const float* __restrict__ xyz,
                                                  int* __restrict__ out_idx,
                                                  float* __restrict__ out_lc) {
    constexpr int T = 256;
    constexpr int PPT = N / T;
    const int b = blockIdx.x;
    const int tid = threadIdx.x;
    const float* xb = xyz + (size_t)b * N * 3;

    float px[PPT], py[PPT], pz[PPT], dd[PPT];
#pragma unroll
    for (int i = 0; i < PPT; ++i) {
        int n = i * T + tid;                 // coalesced
        px[i] = xb[n * 3 + 0];
        py[i] = xb[n * 3 + 1];
        pz[i] = xb[n * 3 + 2];
        dd[i] = 1e10f;
    }
    __shared__ unsigned long long wb[2][8];

    int far = 0;
    for (int m = 0; m < G; ++m) {
        float cx = __ldg(xb + far * 3 + 0);
        float cy = __ldg(xb + far * 3 + 1);
        float cz = __ldg(xb + far * 3 + 2);
        if (tid == 0) {
            out_idx[(size_t)b * G + m] = far;
            float* o = out_lc + ((size_t)b * G + m) * 3;
            o[0] = cx; o[1] = cy; o[2] = cz;
        }
        float bv = -1.0f;
        int bi = 0;
#pragma unroll
        for (int i = 0; i < PPT; ++i) {
            float dx = __fsub_rn(px[i], cx);
            float dy = __fsub_rn(py[i], cy);
            float dz = __fsub_rn(pz[i], cz);
            float d = __fadd_rn(__fadd_rn(__fmul_rn(dx, dx), __fmul_rn(dy, dy)),
                                __fmul_rn(dz, dz));
            float nd = fminf(dd[i], d);
            dd[i] = nd;
            if (nd > bv) { bv = nd; bi = i * T + tid; }   // ascending n: first-max kept
        }
        // dist >= 0 so float bits are monotonic as unsigned. Max dist, tie -> min idx.
        unsigned long long key =
            ((unsigned long long)__float_as_uint(bv) << 32) | (unsigned)(N - 1 - bi);
#pragma unroll
        for (int off = 16; off > 0; off >>= 1) {
            unsigned long long o = __shfl_down_sync(0xffffffffu, key, off);
            if (o > key) key = o;
        }
        if ((tid & 31) == 0) wb[m & 1][tid >> 5] = key;
        __syncthreads();
        unsigned long long best = wb[m & 1][0];
#pragma unroll
        for (int w = 1; w < 8; ++w)
            if (wb[m & 1][w] > best) best = wb[m & 1][w];
        far = N - 1 - (int)(unsigned)(best & 0xffffffffu);
    }
}

// ---------------- gather center features ----------------
template <int N, int G, int C>
__global__ void gather_feat_kernel(const float* __restrict__ feats,
                                   const int* __restrict__ fps,
                                   float* __restrict__ lcx) {
    int i = blockIdx.x * blockDim.x + threadIdx.x;
    int total = BATCH * G * C;
    if (i >= total) return;
    int bg = i / C;
    int c = i - bg * C;
    int b = bg / G;
    int idx = fps[bg];
    lcx[(size_t)bg * C + c] = feats[((size_t)b * N + idx) * C + c];
}

// ---------------- kNN: cached-register local min; only winner rescans ------------
template <int N, int G>
__global__ __launch_bounds__(256) void knn_kernel(const float* __restrict__ xyz,
                                                  const float* __restrict__ lc,
                                                  int* __restrict__ knn) {
    constexpr int T = 256;
    constexpr int PPT = N / T;
    const int bg = blockIdx.x;
    const int b = bg / G;
    const int tid = threadIdx.x;
    __shared__ float sd[N];
    __shared__ unsigned long long wb[2][8];
    const float* xb = xyz + (size_t)b * N * 3;
    float cx = lc[bg * 3 + 0], cy = lc[bg * 3 + 1], cz = lc[bg * 3 + 2];
    float sc = __fadd_rn(__fadd_rn(__fmul_rn(cx, cx), __fmul_rn(cy, cy)),
                         __fmul_rn(cz, cz));
    float bv = __int_as_float(0x7f800000);
    int bi = N;
#pragma unroll
    for (int i = 0; i < PPT; ++i) {
        int n = i * T + tid;                 // coalesced loads, conflict-free STS
        float xx = xb[n * 3 + 0], xy = xb[n * 3 + 1], xz = xb[n * 3 + 2];
        float sx = __fadd_rn(__fadd_rn(__fmul_rn(xx, xx), __fmul_rn(xy, xy)),
                             __fmul_rn(xz, xz));
        float dt = __fadd_rn(__fadd_rn(__fmul_rn(cx, xx), __fmul_rn(cy, xy)),
                             __fmul_rn(cz, xz));
        float d = __fadd_rn(__fsub_rn(sc, __fmul_rn(2.0f, dt)), sx);
        sd[n] = d;
        if (d < bv) { bv = d; bi = n; }      // ascending n: first-min kept
    }
    // order-preserving flip (handles possibly-negative distances)
    unsigned fb = __float_as_uint(bv);
    fb ^= (fb & 0x80000000u) ? 0xFFFFFFFFu : 0x80000000u;
    unsigned long long key = ((unsigned long long)fb << 32) | (unsigned)bi;
    __syncthreads();                          // sd visible to owner rescans

    const float INF = __int_as_float(0x7f800000);
    for (int k = 0; k < KNB; ++k) {
        unsigned long long kk = key;
#pragma unroll
        for (int off = 16; off > 0; off >>= 1) {
            unsigned long long o = __shfl_down_sync(0xffffffffu, kk, off);
            if (o < kk) kk = o;
        }
        if ((tid & 31) == 0) wb[k & 1][tid >> 5] = kk;
        __syncthreads();
        unsigned long long best = wb[k & 1][0];
#pragma unroll
        for (int w = 1; w < 8; ++w)
            if (wb[k & 1][w] < best) best = wb[k & 1][w];
        int win = (int)(unsigned)(best & 0xffffffffu);
        if (tid == 0) knn[(size_t)bg * KNB + k] = win;
        if ((win & (T - 1)) == tid) {
            // I own the winner: poke it out and recompute my cached min.
            sd[win] = INF;
            float nbv = INF;
            int nbi = N;
#pragma unroll
            for (int i = 0; i < PPT; ++i) {
                int n = i * T + tid;
                float v = sd[n];
                if (v < nbv) { nbv = v; nbi = n; }
            }
            unsigned nfb = __float_as_uint(nbv);
            nfb ^= (nfb & 0x80000000u) ? 0xFFFFFFFFu : 0x80000000u;
            key = ((unsigned long long)nfb << 32) | (unsigned)nbi;
        }
    }
}

// ---------------- global std statistics ----------------
__global__ void zero_acc_kernel(double* __restrict__ acc) {
    if (threadIdx.x < 4) acc[threadIdx.x] = 0.0;
}

template <int N, int G, int C>
__global__ __launch_bounds__(256) void stats_kernel(const float* __restrict__ xyz,
                                                    const float* __restrict__ feats,
                                                    const int* __restrict__ knn,
                                                    const float* __restrict__ lcxyz,
                                                    const float* __restrict__ lcx,
                                                    double* __restrict__ acc) {
    const int P = BATCH * G * KNB;
    int p = blockIdx.x * blockDim.x + threadIdx.x;
    float s1 = 0.f, ss1 = 0.f, s2 = 0.f, ss2 = 0.f;
    if (p < P) {
        int b = p / (G * KNB);
        int rg = p - b * (G * KNB);
        int g = rg / KNB;
        int bg = b * G + g;
        int kidx = knn[p];
        const float* kp = xyz + ((size_t)b * N + kidx) * 3;
        const float* lp = lcxyz + (size_t)bg * 3;
#pragma unroll
        for (int j = 0; j < 3; ++j) {
            float d = kp[j] - lp[j];
            s2 += d;
            ss2 += d * d;
        }
        const float4* kf = (const float4*)(feats + ((size_t)b * N + kidx) * C);
        const float4* lf = (const float4*)(lcx + (size_t)bg * C);
#pragma unroll 4
        for (int c = 0; c < C / 4; ++c) {
            float4 a = kf[c], l = lf[c];
            float d0 = a.x - l.x, d1 = a.y - l.y, d2 = a.z - l.z, d3 = a.w - l.w;
            s1 += d0; ss1 += d0 * d0;
            s1 += d1; ss1 += d1 * d1;
            s1 += d2; ss1 += d2 * d2;
            s1 += d3; ss1 += d3 * d3;
        }
    }
    __shared__ double sh[4][8];
    double v[4] = {(double)s1, (double)ss1, (double)s2, (double)ss2};
#pragma unroll
    for (int q = 0; q < 4; ++q) {
        double r = warp_sum_d(v[q]);
        if ((threadIdx.x & 31) == 0) sh[q][threadIdx.x >> 5] = r;
    }
    __syncthreads();
    if (threadIdx.x == 0) {
#pragma unroll
        for (int q = 0; q < 4; ++q) {
            double t = 0;
#pragma unroll
            for (int w = 0; w < 8; ++w) t += sh[q][w];
            atomicAdd(&acc[q], t);
        }
    }
}

__global__ void finalize_kernel(const double* __restrict__ acc, float* __restrict__ inv,
                                double n1, double n2) {
    double v1 = (acc[1] - acc[0] * acc[0] / n1) / (n1 - 1.0);
    double v2 = (acc[3] - acc[2] * acc[2] / n2) / (n2 - 1.0);
    inv[0] = 1.0f / ((float)sqrt(v1) + 1e-5f);
    inv[1] = 1.0f / ((float)sqrt(v2) + 1e-5f);
}

// ---------------- fused LGA + pooling: 1 thread per output channel ---------------
// pooled[b,ch,g] = k_anp(w)+mean_K(w) = 2*mean_K(w)  (k_anp is identity-mean)
template <int N, int G, int C>
__global__ void main_kernel(const float* __restrict__ xyz, const float* __restrict__ feats,
                            const float* __restrict__ Bmat, const int* __restrict__ knn,
                            const float* __restrict__ lcxyz, const float* __restrict__ lcx,
                            const float* __restrict__ inv, float* __restrict__ pool) {
    constexpr int C2 = 2 * C;
    constexpr int F = C / 3;   // my_dim/(2*3)
    constexpr int CH = C / 2;
    __shared__ float sg[KNB][8];   // nx,ny,nz,crx,cry,crz,dt
    __shared__ int skidx[KNB];
    const int bg = blockIdx.x;
    const int b = bg / G;
    const int g = bg - b * G;
    const int ch = threadIdx.x;

    const float lx = lcxyz[bg * 3 + 0];
    const float ly = lcxyz[bg * 3 + 1];
    const float lz = lcxyz[bg * 3 + 2];
    const float inv_x = inv[0];
    const float inv_p = inv[1];

    if (ch < KNB) {
        int kidx = knn[(size_t)bg * KNB + ch];
        skidx[ch] = kidx;
        const float* kp = xyz + ((size_t)b * N + kidx) * 3;
        float nx = (kp[0] - lx) * inv_p;
        float ny = (kp[1] - ly) * inv_p;
        float nz = (kp[2] - lz) * inv_p;
        sg[ch][0] = nx;
        sg[ch][1] = ny;
        sg[ch][2] = nz;
        sg[ch][3] = ny * lz - nz * ly;
        sg[ch][4] = nz * lx - nx * lz;
        sg[ch][5] = nx * ly - ny * lx;
        sg[ch][6] = nx * lx + ny * ly + nz * lz;
    }
    __syncthreads();
    if (ch >= C2) return;

    const int c3 = ch / (2 * F);
    const int r = ch - c3 * (2 * F);
    const int f = r >> 1;
    const int s = r & 1;
    const float de = powf(100.0f, (float)f / (float)F);
    const float lcv = (c3 == 0) ? lx : ((c3 == 1) ? ly : lz);
    const float divL = 1000.0f * lcv / de;
    const float peL = s ? cosf(divL) : sinf(divL);
    const float scl = 1000.0f / de;

    const bool isFourier = (ch >= C);
    float lcf = 0.0f;
    float B0c = 0, B1c = 0, B2c = 0, B3c = 0, B4c = 0, B5c = 0, B6c = 0;
    bool isSin = false;
    if (!isFourier) {
        lcf = lcx[(size_t)bg * C + ch];
    } else {
        int jj = ch - C;
        isSin = (jj < CH);
        int j = isSin ? jj : (jj - CH);
        B0c = Bmat[0 * CH + j];
        B1c = Bmat[1 * CH + j];
        B2c = Bmat[2 * CH + j];
        B3c = Bmat[3 * CH + j];
        B4c = Bmat[4 * CH + j];
        B5c = Bmat[5 * CH + j];
        B6c = Bmat[6 * CH + j];
    }
    float acc = 0.0f;
#pragma unroll 1
    for (int k = 0; k < KNB; ++k) {
        float nc = sg[k][c3];
        float divK = scl * nc;
        float pe = (s ? cosf(divK) : sinf(divK)) + peL;
        float a;
        if (!isFourier) {
            a = (feats[((size_t)b * N + skidx[k]) * C + ch] - lcf) * inv_x;
        } else {
            float proj = B0c * sg[k][0] + B1c * sg[k][1] + B2c * sg[k][2] +
                         B3c * sg[k][3] + B4c * sg[k][4] + B5c * sg[k][5] +
                         B6c * sg[k][6];
            proj *= 6.283185307179586f;
            float t = isSin ? sinf(proj) : cosf(proj);
            float t2 = t * t;
            a = t * t2 * t2;   // sign(t)*|t|^5
        }
        acc += (a + pe) * pe;
    }
    float mval = acc * (1.0f / 24.0f);
    pool[((size_t)b * C2 + ch) * G + g] = mval + mval;
}

// ---------------- BatchNorm (training-mode batch stats) + exact GELU --------------
template <int CO, int G, bool FOUT>
__global__ __launch_bounds__(256) void bn_kernel(const float* __restrict__ pool,
                                                 const float* __restrict__ gamma,
                                                 const float* __restrict__ beta,
                                                 float* __restrict__ out) {
    const int ch = blockIdx.x;
    const int tid = threadIdx.x;
    const int M = BATCH * G;
    float s = 0.f, ss = 0.f;
    for (int i = tid; i < M; i += 256) {
        int b = i / G;
        int g = i - b * G;
        float v = pool[((size_t)b * CO + ch) * G + g];
        s += v;
        ss += v * v;
    }
    __shared__ double sh[2][8];
    double rs = warp_sum_d((double)s);
    double rss = warp_sum_d((double)ss);
    if ((tid & 31) == 0) {
        sh[0][tid >> 5] = rs;
        sh[1][tid >> 5] = rss;
    }
    __syncthreads();
    __shared__ float sm, sr;
    if (tid == 0) {
        double t0 = 0, t1 = 0;
#pragma unroll
        for (int w = 0; w < 8; ++w) {
            t0 += sh[0][w];
            t1 += sh[1][w];
        }
        double mean = t0 / M;
        double var = t1 / M - mean * mean;
        sm = (float)mean;
        sr = rsqrtf((float)var + 1e-5f);
    }
    __syncthreads();
    float mean = sm, rstd = sr;
    float ga = gamma[ch], be = beta[ch];
    for (int i = tid; i < M; i += 256) {
        int b = i / G;
        int g = i - b * G;
        float v = pool[((size_t)b * CO + ch) * G + g];
        float y = (v - mean) * rstd * ga + be;
        float rr = 0.5f * y * (1.0f + erff(y * 0.70710678118654752440f));
        if (FOUT)
            out[((size_t)b * G + g) * CO + ch] = rr;   // feats layout for next stage
        else
            out[((size_t)b * CO + ch) * G + g] = rr;   // final [B,CO,G]
    }
}

// ---------------- launch (two-stream overlap: fps chain hidden under stage work) --
extern "C" void kernel_launch(void* const* d_in, const int* in_sizes, int n_in,
                              void* d_out, int out_size) {
    const float* xyz = (const float*)d_in[0];
    const float* x = (const float*)d_in[1];
    const float* B0 = (const float*)d_in[2];
    const float* B1 = (const float*)d_in[3];
    const float* ga0 = (const float*)d_in[4];
    const float* be0 = (const float*)d_in[5];
    const float* ga1 = (const float*)d_in[6];
    const float* be1 = (const float*)d_in[7];
    float* out = (float*)d_out;

    // Lazily created on the first (uncaptured correctness) call; reused during
    // capture so no non-capturable API runs inside the captured region.
    static cudaStream_t sB = nullptr;
    static cudaEvent_t evRoot, evF0, evB;
    if (sB == nullptr) {
        cudaStreamCreateWithFlags(&sB, cudaStreamNonBlocking);
        cudaEventCreateWithFlags(&evRoot, cudaEventDisableTiming);
        cudaEventCreateWithFlags(&evF0, cudaEventDisableTiming);
        cudaEventCreateWithFlags(&evB, cudaEventDisableTiming);
    }

    int *fps0P, *fps1P, *knn0P, *knn1P;
    float *lc0P, *lc1P, *lcx0P, *lcx1P, *f0P, *f1P, *pool0P, *pool1P;
    double *acc0P, *acc1P;
    float *inv0P, *inv1P;
    cudaGetSymbolAddress((void**)&fps0P, g_fps0);
    cudaGetSymbolAddress((void**)&fps1P, g_fps1);
    cudaGetSymbolAddress((void**)&knn0P, g_knn0);
    cudaGetSymbolAddress((void**)&knn1P, g_knn1);
    cudaGetSymbolAddress((void**)&lc0P, g_lc0);
    cudaGetSymbolAddress((void**)&lc1P, g_lc1);
    cudaGetSymbolAddress((void**)&lcx0P, g_lcx0);
    cudaGetSymbolAddress((void**)&lcx1P, g_lcx1);
    cudaGetSymbolAddress((void**)&f0P, g_feats0);
    cudaGetSymbolAddress((void**)&f1P, g_feats1);
    cudaGetSymbolAddress((void**)&pool0P, g_pool0);
    cudaGetSymbolAddress((void**)&pool1P, g_pool1);
    cudaGetSymbolAddress((void**)&acc0P, g_acc0);
    cudaGetSymbolAddress((void**)&acc1P, g_acc1);
    cudaGetSymbolAddress((void**)&inv0P, g_inv0);
    cudaGetSymbolAddress((void**)&inv1P, g_inv1);

    // ---- fork: stream B runs the latency-bound FPS chain + knn1 ----
    cudaEventRecord(evRoot, 0);
    cudaStreamWaitEvent(sB, evRoot, 0);
    fps_kernel<4096, 2048><<<BATCH, 256, 0, sB>>>(xyz, fps0P, lc0P);
    cudaEventRecord(evF0, sB);                         // lc0 ready
    fps_kernel<2048, 1024><<<BATCH, 256, 0, sB>>>(lc0P, fps1P, lc1P);
    knn_kernel<2048, 1024><<<BATCH * 1024, 256, 0, sB>>>(lc0P, lc1P, knn1P);
    cudaEventRecord(evB, sB);                          // fps1+knn1 ready

    // ---- stream A (default): stage-0 feature path ----
    {
        constexpr int N = 4096, G = 2048, C = 72;
        int tt = BATCH * C * N;
        transpose_kernel<<<(tt + 255) / 256, 256>>>(x, f0P, C, N);
        zero_acc_kernel<<<1, 32>>>(acc0P);
        zero_acc_kernel<<<1, 32>>>(acc1P);
        cudaStreamWaitEvent(0, evF0, 0);               // need lc0 + fps0 indices
        int gl = BATCH * G * C;
        gather_feat_kernel<N, G, C><<<(gl + 255) / 256, 256>>>(f0P, fps0P, lcx0P);
        knn_kernel<N, G><<<BATCH * G, 256>>>(xyz, lc0P, knn0P);
        int P = BATCH * G * KNB;
        stats_kernel<N, G, C><<<(P + 255) / 256, 256>>>(xyz, f0P, knn0P, lc0P, lcx0P,
                                                        acc0P);
        finalize_kernel<<<1, 1>>>(acc0P, inv0P, (double)BATCH * G * KNB * C,
                                  (double)BATCH * G * KNB * 3);
        main_kernel<N, G, C><<<BATCH * G, 160>>>(xyz, f0P, B0, knn0P, lc0P, lcx0P,
                                                 inv0P, pool0P);
        bn_kernel<2 * C, G, true><<<2 * C, 256>>>(pool0P, ga0, be0, f1P);
    }

    // ---- join: stage-1 tail (fps1 + knn1 already done on B) ----
    cudaStreamWaitEvent(0, evB, 0);
    {
        constexpr int N = 2048, G = 1024, C = 144;
        int gl = BATCH * G * C;
        gather_feat_kernel<N, G, C><<<(gl + 255) / 256, 256>>>(f1P, fps1P, lcx1P);
        int P = BATCH * G * KNB;
        stats_kernel<N, G, C><<<(P + 255) / 256, 256>>>(lc0P, f1P, knn1P, lc1P, lcx1P,
                                                        acc1P);
        finalize_kernel<<<1, 1>>>(acc1P, inv1P, (double)BATCH * G * KNB * C,
                                  (double)BATCH * G * KNB * 3);
        main_kernel<N, G, C><<<BATCH * G, 288>>>(lc0P, f1P, B1, knn1P, lc1P, lcx1P,
                                                 inv1P, pool1P);
        bn_kernel<2 * C, G, false><<<2 * C, 256>>>(pool1P, ga1, be1, out);
    }
    (void)in_sizes;
    (void)n_in;
    (void)out_size;
}